// round 10
// baseline (speedup 1.0000x reference)
#include <cuda_runtime.h>

// RSNN single layer: B=64, T=512, N=2048
// spk_{t} = H( mem_t - 0.5 ),  mem_t = 0.96*mem_{t-1}*(1-spk_{t-1}) + x_t + 0.1*(spk_{t-1} @ eff)
// eff = recurrent with zeroed diagonal.
//
// Key idea: spikes are ~95% dense -> compute rec = colsum(eff) - sum over NON-spiking rows.
// Colsums precomputed in fp64 (exact); per-step subtraction sums ~5% of rows in fp32.
// Spike state carried as packed 32-bit masks; membrane state in a __device__ buffer.

#define Bn 64
#define Tn 512
#define Nn 2048
#define NWn (Nn / 32)   // 64 mask words per batch row

__device__ float    g_colsum[Nn];          // sum_{k != n} E[k][n], computed in double
__device__ float    g_diag[Nn];            // E[n][n]
__device__ unsigned g_mask[2][Bn * NWn];   // double-buffered spike bitmasks
__device__ float    g_mem[Bn * Nn];        // membrane state

// ---------------------------------------------------------------------------
// Preprocess: exact (fp64) column sums of E, minus the diagonal.
// Warp-coalesced: at each k, lanes n..n+31 read consecutive E[k*N + n].
// ---------------------------------------------------------------------------
__global__ void prep_kernel(const float* __restrict__ E) {
    int n = blockIdx.x * blockDim.x + threadIdx.x;
    if (n >= Nn) return;
    double s = 0.0;
    #pragma unroll 4
    for (int k = 0; k < Nn; k++) {
        s += (double)__ldg(&E[(size_t)k * Nn + n]);
    }
    float d = __ldg(&E[(size_t)n * Nn + n]);
    g_colsum[n] = (float)(s - (double)d);
    g_diag[n]   = d;
}

// ---------------------------------------------------------------------------
// One time step. Grid: (N/32 ntiles, B/8 batch groups), 256 threads (8 warps).
// Warp handles one batch b across 32 consecutive neurons (one lane per neuron).
// The zero-spike walk is warp-uniform (mask words broadcast via shuffle), so
// there is no divergence and E row-segments are read as 128B coalesced lines
// that stay resident in L2 (E = 16 MB << 126 MB).
// ---------------------------------------------------------------------------
__global__ void __launch_bounds__(256) step_kernel(
    const float* __restrict__ x,
    const float* __restrict__ E,
    float* __restrict__ out,
    int t)
{
    const int lane  = threadIdx.x & 31;
    const int warp  = threadIdx.x >> 5;
    const int ntile = blockIdx.x;             // 0..63
    const int b     = blockIdx.y * 8 + warp;  // 0..63
    const int n     = ntile * 32 + lane;

    float rec      = 0.0f;
    float spk_prev = 0.0f;

    if (t > 0) {
        const unsigned* __restrict__ mrow = g_mask[(t + 1) & 1] + b * NWn;

        // Two coalesced loads fetch the whole 64-word mask row for this batch.
        unsigned mw0 = mrow[lane];
        unsigned mw1 = mrow[32 + lane];

        float acc = 0.0f;  // sum of E[k][n] over NON-spiking k
        #pragma unroll 4
        for (int w = 0; w < NWn; w++) {
            unsigned src = (w < 32) ? mw0 : mw1;
            unsigned m   = ~__shfl_sync(0xffffffffu, src, w & 31);
            int kbase = w * 32;
            while (m) {
                int bit = __ffs((int)m) - 1;
                m &= m - 1;
                acc += __ldg(&E[(size_t)(kbase + bit) * Nn + n]);
            }
        }

        // Own previous spike bit: word index for neuron n is exactly `ntile`.
        unsigned selfw = __shfl_sync(0xffffffffu, (ntile < 32) ? mw0 : mw1, ntile & 31);
        spk_prev = ((selfw >> lane) & 1u) ? 1.0f : 0.0f;

        // Diagonal correction: eff[n][n] == 0, so if neuron n was silent we
        // wrongly accumulated E[n][n] into acc — remove it.
        if (spk_prev == 0.0f) acc = __fsub_rn(acc, g_diag[n]);

        rec = __fsub_rn(g_colsum[n], acc);
    }

    float xv      = x[((size_t)b * Tn + t) * Nn + n];
    // current = x + 0.1 * rec  (separate mul + add, matching the formula)
    float current = __fadd_rn(xv, __fmul_rn(0.1f, rec));

    float mem;
    if (t == 0) {
        mem = current;  // mem0 = 0, spk0 = 0
    } else {
        float mp = g_mem[b * Nn + n];
        // mem = 0.96*mem_prev*(1-spk_prev) + current ; exact when spk_prev==1
        mem = (spk_prev != 0.0f) ? current
                                 : __fadd_rn(__fmul_rn(0.96f, mp), current);
    }

    float spk = (mem - 0.5f >= 0.0f) ? 1.0f : 0.0f;

    out[((size_t)b * Tn + t) * Nn + n] = spk;
    g_mem[b * Nn + n] = mem;

    unsigned word = __ballot_sync(0xffffffffu, spk != 0.0f);
    if (lane == 0) g_mask[t & 1][b * NWn + ntile] = word;
}

// ---------------------------------------------------------------------------
// Entry point: 1 prep launch + 512 dependent step launches (graph-capturable).
// ---------------------------------------------------------------------------
extern "C" void kernel_launch(void* const* d_in, const int* in_sizes, int n_in,
                              void* d_out, int out_size) {
    const float* a0 = (const float*)d_in[0];
    const float* a1 = (const float*)d_in[1];
    const float* x;
    const float* E;
    // Robust to metadata ordering: x has B*T*N elements, recurrent has N*N.
    if (in_sizes[0] == Bn * Tn * Nn) { x = a0; E = a1; }
    else                             { x = a1; E = a0; }

    prep_kernel<<<(Nn + 255) / 256, 256>>>(E);

    dim3 grid(Nn / 32, Bn / 8);
    float* out = (float*)d_out;
    for (int t = 0; t < Tn; t++) {
        step_kernel<<<grid, 256>>>(x, E, out, t);
    }
}

// round 13
// speedup vs baseline: 1.0032x; 1.0032x over previous
#include <cuda_runtime.h>

// RSNN single layer: B=64, T=512, N=2048
// spk_{t} = H( mem_t - 0.5 ),  mem_t = 0.96*mem_{t-1}*(1-spk_{t-1}) + x_t + 0.1*(spk_{t-1} @ eff)
// eff = recurrent with zeroed diagonal.
//
// Key idea: spikes are ~95% dense -> compute rec = colsum(eff) - sum over NON-spiking rows.
// Colsums precomputed in fp64 (exact); per-step subtraction sums ~5% of rows in fp32.
// Spike state carried as packed 32-bit masks; membrane state in a __device__ buffer.

#define Bn 64
#define Tn 512
#define Nn 2048
#define NWn (Nn / 32)   // 64 mask words per batch row

__device__ float    g_colsum[Nn];          // sum_{k != n} E[k][n], computed in double
__device__ float    g_diag[Nn];            // E[n][n]
__device__ unsigned g_mask[2][Bn * NWn];   // double-buffered spike bitmasks
__device__ float    g_mem[Bn * Nn];        // membrane state

// ---------------------------------------------------------------------------
// Preprocess: exact (fp64) column sums of E, minus the diagonal.
// Warp-coalesced: at each k, lanes n..n+31 read consecutive E[k*N + n].
// ---------------------------------------------------------------------------
__global__ void prep_kernel(const float* __restrict__ E) {
    int n = blockIdx.x * blockDim.x + threadIdx.x;
    if (n >= Nn) return;
    double s = 0.0;
    #pragma unroll 4
    for (int k = 0; k < Nn; k++) {
        s += (double)__ldg(&E[(size_t)k * Nn + n]);
    }
    float d = __ldg(&E[(size_t)n * Nn + n]);
    g_colsum[n] = (float)(s - (double)d);
    g_diag[n]   = d;
}

// ---------------------------------------------------------------------------
// One time step. Grid: (N/32 ntiles, B/8 batch groups), 256 threads (8 warps).
// Warp handles one batch b across 32 consecutive neurons (one lane per neuron).
// The zero-spike walk is warp-uniform (mask words broadcast via shuffle), so
// there is no divergence and E row-segments are read as 128B coalesced lines
// that stay resident in L2 (E = 16 MB << 126 MB).
// ---------------------------------------------------------------------------
__global__ void __launch_bounds__(256) step_kernel(
    const float* __restrict__ x,
    const float* __restrict__ E,
    float* __restrict__ out,
    int t)
{
    const int lane  = threadIdx.x & 31;
    const int warp  = threadIdx.x >> 5;
    const int ntile = blockIdx.x;             // 0..63
    const int b     = blockIdx.y * 8 + warp;  // 0..63
    const int n     = ntile * 32 + lane;

    float rec      = 0.0f;
    float spk_prev = 0.0f;

    if (t > 0) {
        const unsigned* __restrict__ mrow = g_mask[(t + 1) & 1] + b * NWn;

        // Two coalesced loads fetch the whole 64-word mask row for this batch.
        unsigned mw0 = mrow[lane];
        unsigned mw1 = mrow[32 + lane];

        float acc = 0.0f;  // sum of E[k][n] over NON-spiking k
        #pragma unroll 4
        for (int w = 0; w < NWn; w++) {
            unsigned src = (w < 32) ? mw0 : mw1;
            unsigned m   = ~__shfl_sync(0xffffffffu, src, w & 31);
            int kbase = w * 32;
            while (m) {
                int bit = __ffs((int)m) - 1;
                m &= m - 1;
                acc += __ldg(&E[(size_t)(kbase + bit) * Nn + n]);
            }
        }

        // Own previous spike bit: word index for neuron n is exactly `ntile`.
        unsigned selfw = __shfl_sync(0xffffffffu, (ntile < 32) ? mw0 : mw1, ntile & 31);
        spk_prev = ((selfw >> lane) & 1u) ? 1.0f : 0.0f;

        // Diagonal correction: eff[n][n] == 0, so if neuron n was silent we
        // wrongly accumulated E[n][n] into acc — remove it.
        if (spk_prev == 0.0f) acc = __fsub_rn(acc, g_diag[n]);

        rec = __fsub_rn(g_colsum[n], acc);
    }

    float xv      = x[((size_t)b * Tn + t) * Nn + n];
    // current = x + 0.1 * rec  (separate mul + add, matching the formula)
    float current = __fadd_rn(xv, __fmul_rn(0.1f, rec));

    float mem;
    if (t == 0) {
        mem = current;  // mem0 = 0, spk0 = 0
    } else {
        float mp = g_mem[b * Nn + n];
        // mem = 0.96*mem_prev*(1-spk_prev) + current ; exact when spk_prev==1
        mem = (spk_prev != 0.0f) ? current
                                 : __fadd_rn(__fmul_rn(0.96f, mp), current);
    }

    float spk = (mem - 0.5f >= 0.0f) ? 1.0f : 0.0f;

    out[((size_t)b * Tn + t) * Nn + n] = spk;
    g_mem[b * Nn + n] = mem;

    unsigned word = __ballot_sync(0xffffffffu, spk != 0.0f);
    if (lane == 0) g_mask[t & 1][b * NWn + ntile] = word;
}

// ---------------------------------------------------------------------------
// Entry point: 1 prep launch + 512 dependent step launches (graph-capturable).
// ---------------------------------------------------------------------------
extern "C" void kernel_launch(void* const* d_in, const int* in_sizes, int n_in,
                              void* d_out, int out_size) {
    const float* a0 = (const float*)d_in[0];
    const float* a1 = (const float*)d_in[1];
    const float* x;
    const float* E;
    // Robust to metadata ordering: x has B*T*N elements, recurrent has N*N.
    if (in_sizes[0] == Bn * Tn * Nn) { x = a0; E = a1; }
    else                             { x = a1; E = a0; }

    prep_kernel<<<(Nn + 255) / 256, 256>>>(E);

    dim3 grid(Nn / 32, Bn / 8);
    float* out = (float*)d_out;
    for (int t = 0; t < Tn; t++) {
        step_kernel<<<grid, 256>>>(x, E, out, t);
    }
}